// round 4
// baseline (speedup 1.0000x reference)
#include <cuda_runtime.h>

// StructuralLoss: fused local-xcorr loss, w=2 (4x4 windows, offsets -1..+2, zero-pad).
// One fused pass: register-rolling warp-strip kernel, no smem, no scratch tensors.

#define NN 4096
#define OUTW 58                 // output columns per warp (64-wide strip minus 6 halo)
#define CHUNK 64                // output rows per warp task
#define NSTRIPS 71              // ceil(4096/58)
#define NCHUNKS (NN / CHUNK)    // 64
#define NTASKS (NSTRIPS * NCHUNKS)
#define WPB 8
#define TPB (WPB * 32)
#define NBLOCKS ((NTASKS + WPB - 1) / WPB)

__device__ double g_sum;

__global__ void xcorr_init() { g_sum = 0.0; }

// Output dtype: float32 (harness __output__); accumulate in double, cast at the end.
__global__ void xcorr_final(float* __restrict__ out) {
    double m = 1.0 - g_sum / ((double)NN * (double)NN);
    out[0] = (float)m;
    out[1] = (float)m;
}

// horizontal 4-tap sum with window offsets [-1..+2] over the warp's 64 columns
// (lane l holds cols 2l, 2l+1 of the strip). 3 shuffles + 4 adds for 2 outputs.
__device__ __forceinline__ float2 hsum4(float2 a) {
    const unsigned FULL = 0xffffffffu;
    float ly = __shfl_up_sync(FULL, a.y, 1);
    float rx = __shfl_down_sync(FULL, a.x, 1);
    float ry = __shfl_down_sync(FULL, a.y, 1);
    float t = a.x + a.y + rx;
    float2 s;
    s.x = ly + t;   // a[m-1]+a[m]+a[m+1]+a[m+2]
    s.y = t + ry;
    return s;
}

__device__ __forceinline__ float2 ldrow(const float* __restrict__ b, int r, bool colok) {
    if (colok && ((unsigned)r < (unsigned)NN)) {
        return *reinterpret_cast<const float2*>(b + (long long)r * NN);
    }
    return make_float2(0.f, 0.f);
}

__device__ __forceinline__ float lterm(float sii, float sjj, float sij) {
    sii = fmaxf(sii, 1e-20f);
    sjj = fmaxf(sjj, 1e-20f);
    float prod = fmaxf(sii * sjj, 1e-30f);   // keep rsqrt out of FTZ range
    float L = sij * rsqrtf(prod);            // |L| <= ~1 by Cauchy-Schwarz
    return fmaxf(L, -1.0f);
}

__global__ void __launch_bounds__(TPB, 2)
xcorr_kernel(const float* __restrict__ img1, const float* __restrict__ img2) {
    int task = blockIdx.x * WPB + (threadIdx.x >> 5);
    if (task >= NTASKS) return;
    int lane = threadIdx.x & 31;
    int strip = task % NSTRIPS;
    int chunk = task / NSTRIPS;
    int i0 = chunk * CHUNK;
    int cstart = strip * OUTW - 2;           // strip covers img cols [cstart, cstart+63]
    int col0 = cstart + 2 * lane;            // this lane's two columns: col0, col0+1 (col0 even)
    bool colok = (col0 >= 0) && (col0 < NN); // both components in/out together (col0 even, NN even)
    bool outok = (lane >= 1) && (lane <= 29) && (col0 < NN);

    const float* b1 = img1 + col0;
    const float* b2 = img2 + col0;

    const float2 z = make_float2(0.f, 0.f);
    float2 x1R[4], x2R[4], h1R[4], h2R[4];
    float2 PiiR[4], PjjR[4], PijR[4];
#pragma unroll
    for (int k = 0; k < 4; ++k) {
        x1R[k] = z; x2R[k] = z; h1R[k] = z; h2R[k] = z;
        PiiR[k] = z; PjjR[k] = z; PijR[k] = z;
    }
    float2 V1 = z, V2 = z, Sii = z, Sjj = z, Sij = z;
    float acc = 0.f;

    // Pipeline: at iteration i we consume img row i+4, produce c row i+2,
    // and emit output row i. 6 warm-up iterations flush zero-initialized rings;
    // output row i only depends on img rows >= i-2, first row loaded is i0-2.
    const int istart = i0 - 6;
    float2 pf1 = ldrow(b1, istart + 4, colok);
    float2 pf2 = ldrow(b2, istart + 4, colok);

#pragma unroll 1
    for (int ib = 0; ib < 72; ib += 4) {   // 6 warmup + 64 output + 2 drain
#pragma unroll
        for (int u = 0; u < 4; ++u) {
            const int i = istart + ib + u;
            const int ks = (u + 2) & 3;    // == i & 3     (istart % 4 == 2)
            const int kr = u;              // == (i+2) & 3

            // consume prefetched row i+4, prefetch row i+5
            float2 a1 = pf1, a2 = pf2;
            x1R[ks] = a1; x2R[ks] = a2;
            pf1 = ldrow(b1, i + 5, colok);
            pf2 = ldrow(b2, i + 5, colok);

            // horizontal 4-sum of new img row; rolling vertical sum (rows i+1..i+4)
            float2 h1 = hsum4(a1);
            float2 h2 = hsum4(a2);
            V1.x += h1.x - h1R[ks].x; V1.y += h1.y - h1R[ks].y;
            V2.x += h2.x - h2R[ks].x; V2.y += h2.y - h2R[ks].y;
            h1R[ks] = h1; h2R[ks] = h2;

            // centered values at row i+2 (zero outside the image = c1/c2 padding)
            bool cv = colok && ((unsigned)(i + 2) < (unsigned)NN);
            float2 xa = x1R[kr], xb = x2R[kr];
            float2 c1, c2;
            c1.x = cv ? (xa.x - V1.x * 0.0625f) : 0.f;
            c1.y = cv ? (xa.y - V1.y * 0.0625f) : 0.f;
            c2.x = cv ? (xb.x - V2.x * 0.0625f) : 0.f;
            c2.y = cv ? (xb.y - V2.y * 0.0625f) : 0.f;

            // products, horizontal 4-sums, rolling vertical 4-sums (rows i-1..i+2)
            float2 pii, pjj, pij;
            pii.x = c1.x * c1.x; pii.y = c1.y * c1.y;
            pjj.x = c2.x * c2.x; pjj.y = c2.y * c2.y;
            pij.x = c1.x * c2.x; pij.y = c1.y * c2.y;

            float2 Pii = hsum4(pii);
            float2 Pjj = hsum4(pjj);
            float2 Pij = hsum4(pij);

            Sii.x += Pii.x - PiiR[kr].x; Sii.y += Pii.y - PiiR[kr].y; PiiR[kr] = Pii;
            Sjj.x += Pjj.x - PjjR[kr].x; Sjj.y += Pjj.y - PjjR[kr].y; PjjR[kr] = Pjj;
            Sij.x += Pij.x - PijR[kr].x; Sij.y += Pij.y - PijR[kr].y; PijR[kr] = Pij;

            // emit output row i
            if (((unsigned)(i - i0) < (unsigned)CHUNK) && outok) {
                acc += lterm(Sii.x, Sjj.x, Sij.x);
                acc += lterm(Sii.y, Sjj.y, Sij.y);
            }
        }
    }

    // reduce: per-thread float partial (<=128 terms, |L|<=1) -> double warp sum -> atomic
    double v = (double)acc;
#pragma unroll
    for (int o = 16; o; o >>= 1) v += __shfl_xor_sync(0xffffffffu, v, o);
    if (lane == 0) atomicAdd(&g_sum, v);
}

extern "C" void kernel_launch(void* const* d_in, const int* in_sizes, int n_in,
                              void* d_out, int out_size) {
    const float* a = (const float*)d_in[0];   // outputs
    const float* b = (const float*)d_in[1];   // labels
    (void)in_sizes; (void)n_in; (void)out_size;
    xcorr_init<<<1, 1>>>();
    xcorr_kernel<<<NBLOCKS, TPB>>>(a, b);
    xcorr_final<<<1, 1>>>((float*)d_out);
}

// round 5
// speedup vs baseline: 1.0005x; 1.0005x over previous
#include <cuda_runtime.h>

// StructuralLoss: fused local-xcorr loss, w=2 (4x4 windows, offsets -1..+2, zero-pad).
// Single-launch version: register-rolling warp-strip stencil + last-block finalize.

#define NN 4096
#define OUTW 58                 // output columns per warp (64-wide strip minus 6 halo)
#define CHUNK 64                // output rows per warp task
#define NSTRIPS 71              // ceil(4096/58)
#define NCHUNKS (NN / CHUNK)    // 64
#define NTASKS (NSTRIPS * NCHUNKS)   // 4544 = 568 * 8 (exact)
#define WPB 8
#define TPB (WPB * 32)
#define NBLOCKS (NTASKS / WPB)  // 568

__device__ double g_sum;        // zero at module load; reset by last block each run
__device__ unsigned g_count;    // wraps to 0 via atomicInc, so stays consistent per replay

// horizontal 4-tap sum with window offsets [-1..+2] over the warp's 64 columns
// (lane l holds cols 2l, 2l+1 of the strip). 3 shuffles + 4 adds for 2 outputs.
__device__ __forceinline__ float2 hsum4(float2 a) {
    const unsigned FULL = 0xffffffffu;
    float ly = __shfl_up_sync(FULL, a.y, 1);
    float rx = __shfl_down_sync(FULL, a.x, 1);
    float ry = __shfl_down_sync(FULL, a.y, 1);
    float t = a.x + a.y + rx;
    float2 s;
    s.x = ly + t;   // a[m-1]+a[m]+a[m+1]+a[m+2]
    s.y = t + ry;
    return s;
}

__device__ __forceinline__ float2 ldrow(const float* __restrict__ b, int r, bool colok) {
    if (colok && ((unsigned)r < (unsigned)NN)) {
        return *reinterpret_cast<const float2*>(b + (long long)r * NN);
    }
    return make_float2(0.f, 0.f);
}

__device__ __forceinline__ float lterm(float sii, float sjj, float sij) {
    sii = fmaxf(sii, 1e-20f);
    sjj = fmaxf(sjj, 1e-20f);
    float prod = fmaxf(sii * sjj, 1e-30f);   // keep rsqrt out of FTZ range
    float L = sij * rsqrtf(prod);            // |L| <= ~1 by Cauchy-Schwarz
    return fmaxf(L, -1.0f);
}

__global__ void __launch_bounds__(TPB, 2)
xcorr_kernel(const float* __restrict__ img1, const float* __restrict__ img2,
             float* __restrict__ out) {
    const int task = blockIdx.x * WPB + (threadIdx.x >> 5);   // always < NTASKS (exact division)
    const int lane = threadIdx.x & 31;
    const int strip = task % NSTRIPS;
    const int chunk = task / NSTRIPS;
    const int i0 = chunk * CHUNK;
    const int cstart = strip * OUTW - 2;     // strip covers img cols [cstart, cstart+63]
    const int col0 = cstart + 2 * lane;      // this lane's two columns: col0, col0+1 (col0 even)
    const bool colok = (col0 >= 0) && (col0 < NN);
    const bool outok = (lane >= 1) && (lane <= 29) && (col0 < NN);

    const float* b1 = img1 + col0;
    const float* b2 = img2 + col0;

    const float2 z = make_float2(0.f, 0.f);
    float2 x1R[4], x2R[4], h1R[4], h2R[4];
    float2 PiiR[4], PjjR[4], PijR[4];
#pragma unroll
    for (int k = 0; k < 4; ++k) {
        x1R[k] = z; x2R[k] = z; h1R[k] = z; h2R[k] = z;
        PiiR[k] = z; PjjR[k] = z; PijR[k] = z;
    }
    float2 V1 = z, V2 = z, Sii = z, Sjj = z, Sij = z;
    float acc = 0.f;

    // Pipeline: at iteration i we consume img row i+4, produce c row i+2,
    // and emit output row i. 6 warm-up iterations flush zero-initialized rings;
    // output row i only depends on img rows >= i-2, first row loaded is i0-2.
    const int istart = i0 - 6;
    float2 pf1 = ldrow(b1, istart + 4, colok);
    float2 pf2 = ldrow(b2, istart + 4, colok);

#pragma unroll 1
    for (int ib = 0; ib < 72; ib += 4) {   // 6 warmup + 64 output + 2 drain
#pragma unroll
        for (int u = 0; u < 4; ++u) {
            const int i = istart + ib + u;
            const int ks = (u + 2) & 3;    // == i & 3     (istart % 4 == 2)
            const int kr = u;              // == (i+2) & 3

            // consume prefetched row i+4, prefetch row i+5
            float2 a1 = pf1, a2 = pf2;
            x1R[ks] = a1; x2R[ks] = a2;
            pf1 = ldrow(b1, i + 5, colok);
            pf2 = ldrow(b2, i + 5, colok);

            // horizontal 4-sum of new img row; rolling vertical sum (rows i+1..i+4)
            float2 h1 = hsum4(a1);
            float2 h2 = hsum4(a2);
            V1.x += h1.x - h1R[ks].x; V1.y += h1.y - h1R[ks].y;
            V2.x += h2.x - h2R[ks].x; V2.y += h2.y - h2R[ks].y;
            h1R[ks] = h1; h2R[ks] = h2;

            // centered values at row i+2 (zero outside the image = c1/c2 padding)
            bool cv = colok && ((unsigned)(i + 2) < (unsigned)NN);
            float2 xa = x1R[kr], xb = x2R[kr];
            float2 c1, c2;
            c1.x = cv ? (xa.x - V1.x * 0.0625f) : 0.f;
            c1.y = cv ? (xa.y - V1.y * 0.0625f) : 0.f;
            c2.x = cv ? (xb.x - V2.x * 0.0625f) : 0.f;
            c2.y = cv ? (xb.y - V2.y * 0.0625f) : 0.f;

            // products, horizontal 4-sums, rolling vertical 4-sums (rows i-1..i+2)
            float2 pii, pjj, pij;
            pii.x = c1.x * c1.x; pii.y = c1.y * c1.y;
            pjj.x = c2.x * c2.x; pjj.y = c2.y * c2.y;
            pij.x = c1.x * c2.x; pij.y = c1.y * c2.y;

            float2 Pii = hsum4(pii);
            float2 Pjj = hsum4(pjj);
            float2 Pij = hsum4(pij);

            Sii.x += Pii.x - PiiR[kr].x; Sii.y += Pii.y - PiiR[kr].y; PiiR[kr] = Pii;
            Sjj.x += Pjj.x - PjjR[kr].x; Sjj.y += Pjj.y - PjjR[kr].y; PjjR[kr] = Pjj;
            Sij.x += Pij.x - PijR[kr].x; Sij.y += Pij.y - PijR[kr].y; PijR[kr] = Pij;

            // emit output row i
            if (((unsigned)(i - i0) < (unsigned)CHUNK) && outok) {
                acc += lterm(Sii.x, Sjj.x, Sij.x);
                acc += lterm(Sii.y, Sjj.y, Sij.y);
            }
        }
    }

    // reduce: per-thread float partial (<=128 terms, |L|<=1) -> double warp sum -> atomic
    double v = (double)acc;
#pragma unroll
    for (int o = 16; o; o >>= 1) v += __shfl_xor_sync(0xffffffffu, v, o);
    if (lane == 0) atomicAdd(&g_sum, v);

    // last-block finalize: makes the whole loss a single launch (graph = 1 node)
    __syncthreads();
    if (threadIdx.x == 0) {
        __threadfence();                                    // my g_sum add visible before count
        unsigned t = atomicInc(&g_count, NBLOCKS - 1);      // wraps to 0 after last block
        if (t == NBLOCKS - 1) {
            __threadfence();                                // all prior adds visible
            double total = atomicAdd(&g_sum, 0.0);          // coherent read at L2
            float m = (float)(1.0 - total / ((double)NN * (double)NN));
            out[0] = m;
            out[1] = m;
            g_sum = 0.0;                                    // reset for next graph replay
            __threadfence();
        }
    }
}

extern "C" void kernel_launch(void* const* d_in, const int* in_sizes, int n_in,
                              void* d_out, int out_size) {
    const float* a = (const float*)d_in[0];   // outputs
    const float* b = (const float*)d_in[1];   // labels
    (void)in_sizes; (void)n_in; (void)out_size;
    xcorr_kernel<<<NBLOCKS, TPB>>>(a, b, (float*)d_out);
}